// round 14
// baseline (speedup 1.0000x reference)
#include <cuda_runtime.h>
#include <cuda_fp16.h>
#include <cstdint>
#include <cstddef>

// ---------------- problem constants ----------------
#define SEQA   4096
#define BATCH  8
#define DM     1024
#define MROWS  (SEQA*BATCH)          // 32768
#define NELEM_ACT ((size_t)MROWS*DM) // 33554432
#define NELEM_W   ((size_t)DM*DM)    // 1048576

static __device__ __forceinline__ float inv_alpha() { return 1.0f/1.5f; }
#define SCORE_SCALE 0.125f           // 1/sqrt(64)

// ---------------- scratch (device globals; allocation-free) ----------------
__device__ __half g_ah[3][MROWS*DM];
__device__ __half g_wh[4][DM*DM];
__device__ __half g_q[MROWS*DM];
__device__ __half g_k[MROWS*DM];
__device__ __half g_v[MROWS*DM];
__device__ __half g_x2[MROWS*DM];

// ---------------- PTX helpers (baseline ISA only: sm_80-era) ----------------
__device__ __forceinline__ uint32_t smem_u32(const void* p) {
    uint32_t r;
    asm("{ .reg .u64 t; cvta.to.shared.u64 t, %1; cvt.u32.u64 %0, t; }"
        : "=r"(r) : "l"(p));
    return r;
}
__device__ __forceinline__ void cpasync16(uint32_t saddr, const void* g) {
    asm volatile("cp.async.cg.shared.global [%0], [%1], 16;"
                 :: "r"(saddr), "l"(g) : "memory");
}
__device__ __forceinline__ void cp_commit() {
    asm volatile("cp.async.commit_group;" ::: "memory");
}
template<int N> __device__ __forceinline__ void cp_wait() {
    asm volatile("cp.async.wait_group %0;" :: "n"(N) : "memory");
}
__device__ __forceinline__ void ldsm4(uint32_t* r, uint32_t addr) {
    asm volatile("ldmatrix.sync.aligned.m8n8.x4.shared.b16 {%0,%1,%2,%3}, [%4];"
                 : "=r"(r[0]), "=r"(r[1]), "=r"(r[2]), "=r"(r[3]) : "r"(addr));
}
__device__ __forceinline__ void mma16816(float* d, const uint32_t* a, const uint32_t* b) {
    asm volatile(
        "mma.sync.aligned.m16n8k16.row.col.f32.f16.f16.f32 "
        "{%0,%1,%2,%3}, {%4,%5,%6,%7}, {%8,%9}, {%0,%1,%2,%3};"
        : "+f"(d[0]), "+f"(d[1]), "+f"(d[2]), "+f"(d[3])
        : "r"(a[0]), "r"(a[1]), "r"(a[2]), "r"(a[3]), "r"(b[0]), "r"(b[1]));
}

// ---------------- conversion kernels: fp32 -> fp16 ----------------
__global__ void __launch_bounds__(256) conv3_fp16_kernel(
    const float4* __restrict__ x0, const float4* __restrict__ x1,
    const float4* __restrict__ x2,
    uint4* __restrict__ h, int n8)
{
    int i0 = (blockIdx.x * blockDim.x + threadIdx.x) * 2;
    if (i0 >= n8) return;
    const int w = blockIdx.y;
    const float4* x = (w == 0) ? x0 : (w == 1) ? x1 : x2;
    uint4* out = h + (size_t)w * n8;

#pragma unroll
    for (int e = 0; e < 2; e++) {
        int i = i0 + e;
        float4 a = x[2*i];
        float4 b = x[2*i+1];
        float v[8] = {a.x, a.y, a.z, a.w, b.x, b.y, b.z, b.w};
        uint32_t hw[4];
#pragma unroll
        for (int j = 0; j < 4; j++) {
            __half2 hp = __floats2half2_rn(v[2*j], v[2*j+1]);
            hw[j] = *reinterpret_cast<uint32_t*>(&hp);
        }
        out[i] = make_uint4(hw[0], hw[1], hw[2], hw[3]);
    }
}

__global__ void __launch_bounds__(256) conv4_fp16_kernel(
    const float4* __restrict__ w0, const float4* __restrict__ w1,
    const float4* __restrict__ w2, const float4* __restrict__ w3,
    uint4* __restrict__ h, int n8)
{
    int i = blockIdx.x * blockDim.x + threadIdx.x;
    if (i >= n8) return;
    const int w = blockIdx.y;
    const float4* x = (w == 0) ? w0 : (w == 1) ? w1 : (w == 2) ? w2 : w3;
    uint4* out = h + (size_t)w * n8;

    float4 a = x[2*i];
    float4 b = x[2*i+1];
    float v[8] = {a.x, a.y, a.z, a.w, b.x, b.y, b.z, b.w};
    uint32_t hw[4];
#pragma unroll
    for (int j = 0; j < 4; j++) {
        __half2 hp = __floats2half2_rn(v[2*j], v[2*j+1]);
        hw[j] = *reinterpret_cast<uint32_t*>(&hp);
    }
    out[i] = make_uint4(hw[0], hw[1], hw[2], hw[3]);
}

// ---------------- single-fp16 HMMA GEMM core (shared by both launchers) -----
#define BM 128
#define BN 128
#define BK 64
#define STAGES 3
#define AB_STAGE 16384                 // 128 rows x 128B (each of A and B)
#define GEMM_SMEM (STAGES * 2 * AB_STAGE)   // 98304
#define NCH 16                         // K=1024 / BK

template<int HALF_OUT>
__device__ __forceinline__ void gemm_core(
    const __half* __restrict__ Ah, const __half* __restrict__ Bh,
    const float* __restrict__ bias, void* __restrict__ Cv,
    char* smem, int bx, int by)
{
    const uint32_t sb = smem_u32(smem);
    const int tid  = threadIdx.x;
    const int lane = tid & 31;
    const int wid  = tid >> 5;        // 0..3
    const int wm   = wid >> 1;        // 0..1 (M 64 each)
    const int wn   = wid & 1;         // 0..1 (N 64 each)
    const int row0 = by * BM;
    const int col0 = bx * BN;         // N fastest-varying

    const int lr = tid >> 3;
    const int lc = tid & 7;

    float acc[4][8][4];
#pragma unroll
    for (int a = 0; a < 4; a++)
#pragma unroll
        for (int b = 0; b < 8; b++)
#pragma unroll
            for (int c = 0; c < 4; c++) acc[a][b][c] = 0.0f;

    auto load_stage = [&](int s, int ch) {
        const int ksub = ch * BK;
        const uint32_t sa  = sb + (uint32_t)s * 2 * AB_STAGE;
        const uint32_t sbB = sa + AB_STAGE;
#pragma unroll
        for (int rep = 0; rep < 8; rep++) {
            int r = lr + rep * 16;
            uint32_t sw = (uint32_t)(r * 128) + ((uint32_t)(lc ^ (r & 7)) << 4);
            cpasync16(sa  + sw, Ah + (size_t)(row0 + r) * DM + ksub + lc * 8);
            cpasync16(sbB + sw, Bh + (size_t)(col0 + r) * DM + ksub + lc * 8);
        }
    };

#pragma unroll
    for (int s = 0; s < STAGES - 1; s++) { load_stage(s, s); cp_commit(); }

    for (int ch = 0; ch < NCH; ch++) {
        cp_wait<STAGES - 2>();
        __syncthreads();

        const int nc = ch + STAGES - 1;
        if (nc < NCH) load_stage(nc % STAGES, nc);
        cp_commit();

        const int s = ch % STAGES;
        const uint32_t sa  = sb + (uint32_t)s * 2 * AB_STAGE;
        const uint32_t sbB = sa + AB_STAGE;

#pragma unroll
        for (int k16 = 0; k16 < 4; k16++) {
            uint32_t afrag[4][4];
#pragma unroll
            for (int mi = 0; mi < 4; mi++) {
                int r   = wm * 64 + mi * 16 + (lane & 15);
                int c16 = k16 * 2 + (lane >> 4);
                ldsm4(afrag[mi], sa + (uint32_t)(r * 128) + ((uint32_t)(c16 ^ (r & 7)) << 4));
            }
            uint32_t bfrag[4][4];
#pragma unroll
            for (int nb = 0; nb < 4; nb++) {
                int r   = wn * 64 + nb * 16 + (lane & 7) + ((lane & 16) ? 8 : 0);
                int c16 = k16 * 2 + ((lane >> 3) & 1);
                ldsm4(bfrag[nb], sbB + (uint32_t)(r * 128) + ((uint32_t)(c16 ^ (r & 7)) << 4));
            }
#pragma unroll
            for (int mi = 0; mi < 4; mi++)
#pragma unroll
                for (int ni = 0; ni < 8; ni++)
                    mma16816(acc[mi][ni], afrag[mi], &bfrag[ni >> 1][(ni & 1) * 2]);
        }
    }

    // ---- epilogue: bias add + store (fp16 or fp32) ----
    const int m_base = row0 + wm * 64;
    const int n_base = col0 + wn * 64;
    const int qr = lane >> 2;
    const int qc = (lane & 3) * 2;
#pragma unroll
    for (int ni = 0; ni < 8; ni++) {
        int colg = n_base + ni * 8 + qc;
        float bx2 = bias[colg], by2 = bias[colg + 1];
#pragma unroll
        for (int mi = 0; mi < 4; mi++) {
            int rg = m_base + mi * 16 + qr;
            float v00 = acc[mi][ni][0] + bx2, v01 = acc[mi][ni][1] + by2;
            float v10 = acc[mi][ni][2] + bx2, v11 = acc[mi][ni][3] + by2;
            if (HALF_OUT) {
                __half* C = (__half*)Cv;
                __half2 h0 = __floats2half2_rn(v00, v01);
                __half2 h1 = __floats2half2_rn(v10, v11);
                *(uint32_t*)(C + (size_t)rg * DM + colg)       = *(uint32_t*)&h0;
                *(uint32_t*)(C + (size_t)(rg + 8) * DM + colg) = *(uint32_t*)&h1;
            } else {
                float* C = (float*)Cv;
                *(float2*)(C + (size_t)rg * DM + colg)       = make_float2(v00, v01);
                *(float2*)(C + (size_t)(rg + 8) * DM + colg) = make_float2(v10, v11);
            }
        }
    }
}

// merged Q/K/V projection: grid.z = 3 selects (A, bias, C); one tail not three
__global__ void __launch_bounds__(128, 2) gemm_qkv(
    const __half* __restrict__ Ah0, const __half* __restrict__ Wh,
    const float* __restrict__ bq, const float* __restrict__ bk,
    const float* __restrict__ bv,
    __half* __restrict__ Cq, __half* __restrict__ Ck, __half* __restrict__ Cv2)
{
    extern __shared__ __align__(1024) char smem[];
    const int z = blockIdx.z;
    const __half* Ah = Ah0 + (size_t)z * NELEM_ACT;
    const __half* Bh = Wh  + (size_t)z * NELEM_W;
    const float* bias = (z == 0) ? bq : (z == 1) ? bk : bv;
    __half* C = (z == 0) ? Cq : (z == 1) ? Ck : Cv2;
    gemm_core<1>(Ah, Bh, bias, C, smem, blockIdx.x, blockIdx.y);
}

// final output projection (fp32 out)
__global__ void __launch_bounds__(128, 2) gemm_out(
    const __half* __restrict__ Ah, const __half* __restrict__ Bh,
    const float* __restrict__ bias, float* __restrict__ C)
{
    extern __shared__ __align__(1024) char smem[];
    gemm_core<0>(Ah, Bh, bias, C, smem, blockIdx.x, blockIdx.y);
}

// ---------------- head-mixing sparsemax attention, tensor-core scores -------
// ONE WARP PER TOKEN (8 tokens/block). Scores via mma.m16n8k16 on fp16 Q/K.
// Ps (fp32 score/prob tile, 16x17) ALIASES Qt's storage — Qt is dead after the
// score mma (all Q ldsm complete, in-warp program order, before Ps stores).
// Per-warp span: Qt/Ps 2304B | Kt 2304B | Vt 4352B = 8960B; 8 warps = 70KB
// -> 3 CTAs/SM (215KB), 24 warps: +50% MLP for the DRAM-bound fill phase.
#define AT_WSPAN 8960
#define ATT_SMEM (8 * AT_WSPAN)
__global__ void __launch_bounds__(256) attn_kernel(
    const __half* __restrict__ Q, const __half* __restrict__ K,
    const __half* __restrict__ V, __half* __restrict__ x2)
{
    extern __shared__ __align__(1024) char asmem[];
    const int lane = threadIdx.x & 31;
    const int wid  = threadIdx.x >> 5;
    const int m = blockIdx.x * 8 + wid;
    const int a = m >> 3, b = m & 7;

    char* ws = asmem + wid * AT_WSPAN;
    __half* Qt = (__half*)ws;              // 16 rows x 72 halves (144B rows)
    float*  Ps = (float*)ws;               // 16 x 17 fp32 — aliases Qt (dead after scores)
    __half* Kt = (__half*)(ws + 2304);     // 16 rows x 72 halves
    float*  Vt = (float*)(ws + 4608);      // 16 rows x 68 floats (272B rows)

    // ---- fill: lane covers halves [lane*32, lane*32+32) of each 1024-row ----
    {
        const int r  = lane >> 1;            // row 0..15
        const int cb = (lane & 1) * 32;      // col base 0/32
        const uint4* qg = (const uint4*)(Q + (size_t)m * DM);
        const uint4* kg = (const uint4*)(K + (size_t)m * DM);
        const uint4* vg = (const uint4*)(V + (size_t)m * DM);
#pragma unroll
        for (int j = 0; j < 4; j++) {
            *(uint4*)(Qt + r * 72 + cb + j * 8) = qg[lane * 4 + j];
            *(uint4*)(Kt + r * 72 + cb + j * 8) = kg[lane * 4 + j];
            uint4 vv = vg[lane * 4 + j];
            __half2 h0 = *(__half2*)&vv.x, h1 = *(__half2*)&vv.y;
            __half2 h2 = *(__half2*)&vv.z, h3 = *(__half2*)&vv.w;
            *(float4*)(Vt + r * 68 + cb + j * 8) = make_float4(
                __low2float(h0), __high2float(h0), __low2float(h1), __high2float(h1));
            *(float4*)(Vt + r * 68 + cb + j * 8 + 4) = make_float4(
                __low2float(h2), __high2float(h2), __low2float(h3), __high2float(h3));
        }
    }
    __syncwarp();

    // ---- scores via mma: S = Q @ K^T (m16 n16 k64) ----
    {
        const uint32_t sQ = smem_u32(Qt);
        const uint32_t sK = smem_u32(Kt);
        const int ar = lane & 15, ac = lane >> 4;
        const int br = (lane & 7) + ((lane & 16) ? 8 : 0);
        const int bc = (lane >> 3) & 1;
        float S0[4] = {0, 0, 0, 0};
        float S1[4] = {0, 0, 0, 0};
#pragma unroll
        for (int k16 = 0; k16 < 4; k16++) {
            uint32_t af[4], bf[4];
            ldsm4(af, sQ + (uint32_t)(ar * 144) + (uint32_t)(k16 * 2 + ac) * 16);
            ldsm4(bf, sK + (uint32_t)(br * 144) + (uint32_t)(k16 * 2 + bc) * 16);
            mma16816(S0, af, &bf[0]);
            mma16816(S1, af, &bf[2]);
        }
        __syncwarp();   // all lanes' Q ldsm complete before Ps overwrites Qt
        const int qr = lane >> 2;
        const int qc = (lane & 3) * 2;
        Ps[qr * 17 + qc]           = S0[0] * SCORE_SCALE;
        Ps[qr * 17 + qc + 1]       = S0[1] * SCORE_SCALE;
        Ps[(qr + 8) * 17 + qc]     = S0[2] * SCORE_SCALE;
        Ps[(qr + 8) * 17 + qc + 1] = S0[3] * SCORE_SCALE;
        Ps[qr * 17 + 8 + qc]           = S1[0] * SCORE_SCALE;
        Ps[qr * 17 + 8 + qc + 1]       = S1[1] * SCORE_SCALE;
        Ps[(qr + 8) * 17 + 8 + qc]     = S1[2] * SCORE_SCALE;
        Ps[(qr + 8) * 17 + 8 + qc + 1] = S1[3] * SCORE_SCALE;
    }
    __syncwarp();

    // ---- sparsemax over each head's 16 scores (lanes 0..15) ----
    if (lane < 16) {
        float z[16];
#pragma unroll
        for (int i = 0; i < 16; i++) z[i] = Ps[lane * 17 + i] * inv_alpha();
#pragma unroll
        for (int k = 2; k <= 16; k <<= 1) {
#pragma unroll
            for (int j = k >> 1; j > 0; j >>= 1) {
#pragma unroll
                for (int i = 0; i < 16; i++) {
                    int l = i ^ j;
                    if (l > i) {
                        bool up = ((i & k) == 0);
                        float zi = z[i], zl = z[l];
                        bool sw = up ? (zi > zl) : (zi < zl);
                        if (sw) { z[i] = zl; z[l] = zi; }
                    }
                }
            }
        }
        float cum = 0.0f, csel = 0.0f;
        int kc = 1;
#pragma unroll
        for (int r = 1; r <= 16; r++) {
            float v = z[16 - r];
            cum += v;
            if (v * (float)r > cum - 1.0f) { kc = r; csel = cum; }
        }
        float tau = (csel - 1.0f) / (float)kc;
#pragma unroll
        for (int i = 0; i < 16; i++) {
            float p = Ps[lane * 17 + i] * inv_alpha() - tau;
            Ps[lane * 17 + i] = p > 0.0f ? p : 0.0f;
        }
    }
    __syncwarp();

    // ---- AV: lane -> (h = lane&15, d-window = (lane>>4)*32); original order --
    {
        const int h  = lane & 15;
        const int dw = (lane >> 4) * 32;
        float o[32];
#pragma unroll
        for (int j = 0; j < 32; j++) o[j] = 0.0f;
#pragma unroll
        for (int g = 0; g < 16; g++) {
            float p = Ps[h * 17 + g];
            const float4* vr = (const float4*)(Vt + g * 68 + dw);
#pragma unroll
            for (int j = 0; j < 8; j++) {
                float4 v = vr[j];
                o[j*4 + 0] = fmaf(p, v.x, o[j*4 + 0]);
                o[j*4 + 1] = fmaf(p, v.y, o[j*4 + 1]);
                o[j*4 + 2] = fmaf(p, v.z, o[j*4 + 2]);
                o[j*4 + 3] = fmaf(p, v.w, o[j*4 + 3]);
            }
        }
        const size_t m2  = ((size_t)(h * 256 + (a >> 4))) * 8 + (size_t)b;
        const int    col = (a & 15) * 64 + dw;
        __half* dst = x2 + m2 * DM + col;
#pragma unroll
        for (int j = 0; j < 8; j++) {
            __half2 p0 = __floats2half2_rn(o[j*4 + 0], o[j*4 + 1]);
            __half2 p1 = __floats2half2_rn(o[j*4 + 2], o[j*4 + 3]);
            *(uint2*)(dst + j * 4) = make_uint2(*(uint32_t*)&p0, *(uint32_t*)&p1);
        }
    }
}

// ---------------- launcher ----------------
extern "C" void kernel_launch(void* const* d_in, const int* in_sizes, int n_in,
                              void* d_out, int out_size)
{
    (void)in_sizes; (void)n_in; (void)out_size;

    void *pah, *pwh, *pq, *pk, *pv, *px2;
    cudaGetSymbolAddress(&pah, g_ah);
    cudaGetSymbolAddress(&pwh, g_wh);
    cudaGetSymbolAddress(&pq,  g_q);
    cudaGetSymbolAddress(&pk,  g_k);
    cudaGetSymbolAddress(&pv,  g_v);
    cudaGetSymbolAddress(&px2, g_x2);

    __half* ah   = (__half*)pah;
    __half* wh   = (__half*)pwh;
    __half* qbuf = (__half*)pq;
    __half* kbuf = (__half*)pk;
    __half* vbuf = (__half*)pv;
    __half* x2   = (__half*)px2;

    cudaFuncSetAttribute(gemm_qkv, cudaFuncAttributeMaxDynamicSharedMemorySize, GEMM_SMEM);
    cudaFuncSetAttribute(gemm_out, cudaFuncAttributeMaxDynamicSharedMemorySize, GEMM_SMEM);
    cudaFuncSetAttribute(attn_kernel, cudaFuncAttributeMaxDynamicSharedMemorySize, ATT_SMEM);

    // 1) convert activations (query/key/value) to fp16 — one launch
    const int actN8 = (int)(NELEM_ACT / 8);
    conv3_fp16_kernel<<<dim3(actN8 / 512, 3), 256>>>(
        (const float4*)d_in[0], (const float4*)d_in[1], (const float4*)d_in[2],
        (uint4*)ah, actN8);

    // 2) convert weights (Wq,Wk,Wv,Wo) to fp16 — one launch
    const int wN8 = (int)(NELEM_W / 8);
    conv4_fp16_kernel<<<dim3(wN8 / 256, 4), 256>>>(
        (const float4*)d_in[3], (const float4*)d_in[5],
        (const float4*)d_in[7], (const float4*)d_in[9],
        (uint4*)wh, wN8);

    // 3) Q+K+V projections in ONE launch (grid.z = 3); N-fastest for A reuse
    dim3 qkvgrid(DM / BN, MROWS / BM, 3);   // (8, 256, 3)
    gemm_qkv<<<qkvgrid, 128, GEMM_SMEM>>>(
        ah, wh,
        (const float*)d_in[4], (const float*)d_in[6], (const float*)d_in[8],
        qbuf, kbuf, vbuf);

    // 4) sparsemax attention (tensor-core scores) -> permuted X2 (fp16)
    attn_kernel<<<MROWS / 8, 256, ATT_SMEM>>>(qbuf, kbuf, vbuf, x2);

    // 5) output projection straight into d_out (fp32)
    dim3 ggrid(DM / BN, MROWS / BM);        // (8, 256)
    gemm_out<<<ggrid, 128, GEMM_SMEM>>>(
        x2, wh + 3 * NELEM_W, (const float*)d_in[10], (float*)d_out);
}

// round 16
// speedup vs baseline: 1.0349x; 1.0349x over previous
#include <cuda_runtime.h>
#include <cuda_fp16.h>
#include <cstdint>
#include <cstddef>

// ---------------- problem constants ----------------
#define SEQA   4096
#define BATCH  8
#define DM     1024
#define MROWS  (SEQA*BATCH)          // 32768
#define NELEM_ACT ((size_t)MROWS*DM) // 33554432
#define NELEM_W   ((size_t)DM*DM)    // 1048576

static __device__ __forceinline__ float inv_alpha() { return 1.0f/1.5f; }
#define SCORE_SCALE 0.125f           // 1/sqrt(64)

// ---------------- scratch (device globals; allocation-free) ----------------
__device__ __half g_ah[3][MROWS*DM];
__device__ __half g_wh[4][DM*DM];
__device__ __half g_q[MROWS*DM];
__device__ __half g_k[MROWS*DM];
__device__ __half g_v[MROWS*DM];
__device__ __half g_x2[MROWS*DM];

// ---------------- PTX helpers (baseline ISA only: sm_80-era) ----------------
__device__ __forceinline__ uint32_t smem_u32(const void* p) {
    uint32_t r;
    asm("{ .reg .u64 t; cvta.to.shared.u64 t, %1; cvt.u32.u64 %0, t; }"
        : "=r"(r) : "l"(p));
    return r;
}
__device__ __forceinline__ void cpasync16(uint32_t saddr, const void* g) {
    asm volatile("cp.async.cg.shared.global [%0], [%1], 16;"
                 :: "r"(saddr), "l"(g) : "memory");
}
__device__ __forceinline__ void cp_commit() {
    asm volatile("cp.async.commit_group;" ::: "memory");
}
template<int N> __device__ __forceinline__ void cp_wait() {
    asm volatile("cp.async.wait_group %0;" :: "n"(N) : "memory");
}
__device__ __forceinline__ void ldsm4(uint32_t* r, uint32_t addr) {
    asm volatile("ldmatrix.sync.aligned.m8n8.x4.shared.b16 {%0,%1,%2,%3}, [%4];"
                 : "=r"(r[0]), "=r"(r[1]), "=r"(r[2]), "=r"(r[3]) : "r"(addr));
}
__device__ __forceinline__ void ldsm4t(uint32_t* r, uint32_t addr) {
    asm volatile("ldmatrix.sync.aligned.m8n8.x4.trans.shared.b16 {%0,%1,%2,%3}, [%4];"
                 : "=r"(r[0]), "=r"(r[1]), "=r"(r[2]), "=r"(r[3]) : "r"(addr));
}
__device__ __forceinline__ void mma16816(float* d, const uint32_t* a, const uint32_t* b) {
    asm volatile(
        "mma.sync.aligned.m16n8k16.row.col.f32.f16.f16.f32 "
        "{%0,%1,%2,%3}, {%4,%5,%6,%7}, {%8,%9}, {%0,%1,%2,%3};"
        : "+f"(d[0]), "+f"(d[1]), "+f"(d[2]), "+f"(d[3])
        : "r"(a[0]), "r"(a[1]), "r"(a[2]), "r"(a[3]), "r"(b[0]), "r"(b[1]));
}

// ---------------- conversion kernels: fp32 -> fp16 ----------------
__global__ void __launch_bounds__(256) conv3_fp16_kernel(
    const float4* __restrict__ x0, const float4* __restrict__ x1,
    const float4* __restrict__ x2,
    uint4* __restrict__ h, int n8)
{
    int i0 = (blockIdx.x * blockDim.x + threadIdx.x) * 2;
    if (i0 >= n8) return;
    const int w = blockIdx.y;
    const float4* x = (w == 0) ? x0 : (w == 1) ? x1 : x2;
    uint4* out = h + (size_t)w * n8;

#pragma unroll
    for (int e = 0; e < 2; e++) {
        int i = i0 + e;
        float4 a = x[2*i];
        float4 b = x[2*i+1];
        float v[8] = {a.x, a.y, a.z, a.w, b.x, b.y, b.z, b.w};
        uint32_t hw[4];
#pragma unroll
        for (int j = 0; j < 4; j++) {
            __half2 hp = __floats2half2_rn(v[2*j], v[2*j+1]);
            hw[j] = *reinterpret_cast<uint32_t*>(&hp);
        }
        out[i] = make_uint4(hw[0], hw[1], hw[2], hw[3]);
    }
}

__global__ void __launch_bounds__(256) conv4_fp16_kernel(
    const float4* __restrict__ w0, const float4* __restrict__ w1,
    const float4* __restrict__ w2, const float4* __restrict__ w3,
    uint4* __restrict__ h, int n8)
{
    int i = blockIdx.x * blockDim.x + threadIdx.x;
    if (i >= n8) return;
    const int w = blockIdx.y;
    const float4* x = (w == 0) ? w0 : (w == 1) ? w1 : (w == 2) ? w2 : w3;
    uint4* out = h + (size_t)w * n8;

    float4 a = x[2*i];
    float4 b = x[2*i+1];
    float v[8] = {a.x, a.y, a.z, a.w, b.x, b.y, b.z, b.w};
    uint32_t hw[4];
#pragma unroll
    for (int j = 0; j < 4; j++) {
        __half2 hp = __floats2half2_rn(v[2*j], v[2*j+1]);
        hw[j] = *reinterpret_cast<uint32_t*>(&hp);
    }
    out[i] = make_uint4(hw[0], hw[1], hw[2], hw[3]);
}

// ---------------- single-fp16 HMMA GEMM core (shared by both launchers) -----
#define BM 128
#define BN 128
#define BK 64
#define STAGES 3
#define AB_STAGE 16384                 // 128 rows x 128B (each of A and B)
#define GEMM_SMEM (STAGES * 2 * AB_STAGE)   // 98304
#define NCH 16                         // K=1024 / BK

template<int HALF_OUT>
__device__ __forceinline__ void gemm_core(
    const __half* __restrict__ Ah, const __half* __restrict__ Bh,
    const float* __restrict__ bias, void* __restrict__ Cv,
    char* smem, int bx, int by)
{
    const uint32_t sb = smem_u32(smem);
    const int tid  = threadIdx.x;
    const int lane = tid & 31;
    const int wid  = tid >> 5;        // 0..3
    const int wm   = wid >> 1;        // 0..1 (M 64 each)
    const int wn   = wid & 1;         // 0..1 (N 64 each)
    const int row0 = by * BM;
    const int col0 = bx * BN;         // N fastest-varying

    const int lr = tid >> 3;
    const int lc = tid & 7;

    float acc[4][8][4];
#pragma unroll
    for (int a = 0; a < 4; a++)
#pragma unroll
        for (int b = 0; b < 8; b++)
#pragma unroll
            for (int c = 0; c < 4; c++) acc[a][b][c] = 0.0f;

    auto load_stage = [&](int s, int ch) {
        const int ksub = ch * BK;
        const uint32_t sa  = sb + (uint32_t)s * 2 * AB_STAGE;
        const uint32_t sbB = sa + AB_STAGE;
#pragma unroll
        for (int rep = 0; rep < 8; rep++) {
            int r = lr + rep * 16;
            uint32_t sw = (uint32_t)(r * 128) + ((uint32_t)(lc ^ (r & 7)) << 4);
            cpasync16(sa  + sw, Ah + (size_t)(row0 + r) * DM + ksub + lc * 8);
            cpasync16(sbB + sw, Bh + (size_t)(col0 + r) * DM + ksub + lc * 8);
        }
    };

#pragma unroll
    for (int s = 0; s < STAGES - 1; s++) { load_stage(s, s); cp_commit(); }

    for (int ch = 0; ch < NCH; ch++) {
        cp_wait<STAGES - 2>();
        __syncthreads();

        const int nc = ch + STAGES - 1;
        if (nc < NCH) load_stage(nc % STAGES, nc);
        cp_commit();

        const int s = ch % STAGES;
        const uint32_t sa  = sb + (uint32_t)s * 2 * AB_STAGE;
        const uint32_t sbB = sa + AB_STAGE;

#pragma unroll
        for (int k16 = 0; k16 < 4; k16++) {
            uint32_t afrag[4][4];
#pragma unroll
            for (int mi = 0; mi < 4; mi++) {
                int r   = wm * 64 + mi * 16 + (lane & 15);
                int c16 = k16 * 2 + (lane >> 4);
                ldsm4(afrag[mi], sa + (uint32_t)(r * 128) + ((uint32_t)(c16 ^ (r & 7)) << 4));
            }
            uint32_t bfrag[4][4];
#pragma unroll
            for (int nb = 0; nb < 4; nb++) {
                int r   = wn * 64 + nb * 16 + (lane & 7) + ((lane & 16) ? 8 : 0);
                int c16 = k16 * 2 + ((lane >> 3) & 1);
                ldsm4(bfrag[nb], sbB + (uint32_t)(r * 128) + ((uint32_t)(c16 ^ (r & 7)) << 4));
            }
#pragma unroll
            for (int mi = 0; mi < 4; mi++)
#pragma unroll
                for (int ni = 0; ni < 8; ni++)
                    mma16816(acc[mi][ni], afrag[mi], &bfrag[ni >> 1][(ni & 1) * 2]);
        }
    }

    // ---- epilogue: bias add + store (fp16 or fp32) ----
    const int m_base = row0 + wm * 64;
    const int n_base = col0 + wn * 64;
    const int qr = lane >> 2;
    const int qc = (lane & 3) * 2;
#pragma unroll
    for (int ni = 0; ni < 8; ni++) {
        int colg = n_base + ni * 8 + qc;
        float bx2 = bias[colg], by2 = bias[colg + 1];
#pragma unroll
        for (int mi = 0; mi < 4; mi++) {
            int rg = m_base + mi * 16 + qr;
            float v00 = acc[mi][ni][0] + bx2, v01 = acc[mi][ni][1] + by2;
            float v10 = acc[mi][ni][2] + bx2, v11 = acc[mi][ni][3] + by2;
            if (HALF_OUT) {
                __half* C = (__half*)Cv;
                __half2 h0 = __floats2half2_rn(v00, v01);
                __half2 h1 = __floats2half2_rn(v10, v11);
                *(uint32_t*)(C + (size_t)rg * DM + colg)       = *(uint32_t*)&h0;
                *(uint32_t*)(C + (size_t)(rg + 8) * DM + colg) = *(uint32_t*)&h1;
            } else {
                float* C = (float*)Cv;
                *(float2*)(C + (size_t)rg * DM + colg)       = make_float2(v00, v01);
                *(float2*)(C + (size_t)(rg + 8) * DM + colg) = make_float2(v10, v11);
            }
        }
    }
}

// merged Q/K/V projection: grid.z = 3 selects (A, bias, C); one tail not three
__global__ void __launch_bounds__(128, 2) gemm_qkv(
    const __half* __restrict__ Ah0, const __half* __restrict__ Wh,
    const float* __restrict__ bq, const float* __restrict__ bk,
    const float* __restrict__ bv,
    __half* __restrict__ Cq, __half* __restrict__ Ck, __half* __restrict__ Cv2)
{
    extern __shared__ __align__(1024) char smem[];
    const int z = blockIdx.z;
    const __half* Ah = Ah0 + (size_t)z * NELEM_ACT;
    const __half* Bh = Wh  + (size_t)z * NELEM_W;
    const float* bias = (z == 0) ? bq : (z == 1) ? bk : bv;
    __half* C = (z == 0) ? Cq : (z == 1) ? Ck : Cv2;
    gemm_core<1>(Ah, Bh, bias, C, smem, blockIdx.x, blockIdx.y);
}

// final output projection (fp32 out)
__global__ void __launch_bounds__(128, 2) gemm_out(
    const __half* __restrict__ Ah, const __half* __restrict__ Bh,
    const float* __restrict__ bias, float* __restrict__ C)
{
    extern __shared__ __align__(1024) char smem[];
    gemm_core<0>(Ah, Bh, bias, C, smem, blockIdx.x, blockIdx.y);
}

// ---------------- head-mixing sparsemax attention, full tensor-core ---------
// ONE WARP PER TOKEN (8 tokens/block). Scores AND AV on mma.m16n8k16.
// Per-warp layout (6912B, 8 warps = 55296B/block -> 3-4 CTAs/SM):
//   ws+0    : Qt fp16 16x72 (2304B); Ps fp32 16x18 (1152B) aliases it after
//             scores (EVEN stride 18 -> all float2 accesses 8B-aligned);
//             Dst fp32 16x68 (4352B) aliases Qt+Kt after AV mma.
//   ws+2304 : Kt fp16 16x72
//   ws+4608 : Vt fp16 16x72  (V stays fp16 — it IS the fp16 input, exact)
// New rounding vs R14: P -> fp16 for the AV mma (predicted +~2.4e-4 in quad).
#define PS_STR 18
#define AT_WSPAN 6912
#define ATT_SMEM (8 * AT_WSPAN)
__global__ void __launch_bounds__(256, 3) attn_kernel(
    const __half* __restrict__ Q, const __half* __restrict__ K,
    const __half* __restrict__ V, __half* __restrict__ x2)
{
    extern __shared__ __align__(1024) char asmem[];
    const int lane = threadIdx.x & 31;
    const int wid  = threadIdx.x >> 5;
    const int m = blockIdx.x * 8 + wid;
    const int a = m >> 3, b = m & 7;

    char* ws = asmem + wid * AT_WSPAN;
    __half* Qt = (__half*)ws;              // 16 x 72 halves (144B rows)
    float*  Ps = (float*)ws;               // 16 x 18 fp32 — aliases Qt
    float*  Dst = (float*)ws;              // 16 x 68 fp32 — aliases Qt+Kt
    __half* Kt = (__half*)(ws + 2304);     // 16 x 72 halves
    __half* Vt = (__half*)(ws + 4608);     // 16 x 72 halves

    // ---- fill: lane covers halves [lane*32, lane*32+32) of each 1024-row ----
    {
        const int r  = lane >> 1;            // row 0..15
        const int cb = (lane & 1) * 32;      // col base 0/32
        const uint4* qg = (const uint4*)(Q + (size_t)m * DM);
        const uint4* kg = (const uint4*)(K + (size_t)m * DM);
        const uint4* vg = (const uint4*)(V + (size_t)m * DM);
#pragma unroll
        for (int j = 0; j < 4; j++) {
            *(uint4*)(Qt + r * 72 + cb + j * 8) = qg[lane * 4 + j];
            *(uint4*)(Kt + r * 72 + cb + j * 8) = kg[lane * 4 + j];
            *(uint4*)(Vt + r * 72 + cb + j * 8) = vg[lane * 4 + j];
        }
    }
    __syncwarp();

    // ---- scores via mma: S = Q @ K^T (m16 n16 k64) ----
    {
        const uint32_t sQ = smem_u32(Qt);
        const uint32_t sK = smem_u32(Kt);
        const int ar = lane & 15, ac = lane >> 4;
        const int br = (lane & 7) + ((lane & 16) ? 8 : 0);
        const int bc = (lane >> 3) & 1;
        float S0[4] = {0, 0, 0, 0};
        float S1[4] = {0, 0, 0, 0};
#pragma unroll
        for (int k16 = 0; k16 < 4; k16++) {
            uint32_t af[4], bf[4];
            ldsm4(af, sQ + (uint32_t)(ar * 144) + (uint32_t)(k16 * 2 + ac) * 16);
            ldsm4(bf, sK + (uint32_t)(br * 144) + (uint32_t)(k16 * 2 + bc) * 16);
            mma16816(S0, af, &bf[0]);
            mma16816(S1, af, &bf[2]);
        }
        __syncwarp();   // all lanes' Q ldsm complete before Ps overwrites Qt
        const int qr = lane >> 2;
        const int qc = (lane & 3) * 2;
        Ps[qr * PS_STR + qc]           = S0[0] * SCORE_SCALE;
        Ps[qr * PS_STR + qc + 1]       = S0[1] * SCORE_SCALE;
        Ps[(qr + 8) * PS_STR + qc]     = S0[2] * SCORE_SCALE;
        Ps[(qr + 8) * PS_STR + qc + 1] = S0[3] * SCORE_SCALE;
        Ps[qr * PS_STR + 8 + qc]           = S1[0] * SCORE_SCALE;
        Ps[qr * PS_STR + 8 + qc + 1]       = S1[1] * SCORE_SCALE;
        Ps[(qr + 8) * PS_STR + 8 + qc]     = S1[2] * SCORE_SCALE;
        Ps[(qr + 8) * PS_STR + 8 + qc + 1] = S1[3] * SCORE_SCALE;
    }
    __syncwarp();

    // ---- sparsemax over each head's 16 scores (lanes 0..15) ----
    if (lane < 16) {
        float z[16];
#pragma unroll
        for (int i = 0; i < 16; i++) z[i] = Ps[lane * PS_STR + i] * inv_alpha();
#pragma unroll
        for (int k = 2; k <= 16; k <<= 1) {
#pragma unroll
            for (int j = k >> 1; j > 0; j >>= 1) {
#pragma unroll
                for (int i = 0; i < 16; i++) {
                    int l = i ^ j;
                    if (l > i) {
                        bool up = ((i & k) == 0);
                        float zi = z[i], zl = z[l];
                        bool sw = up ? (zi > zl) : (zi < zl);
                        if (sw) { z[i] = zl; z[l] = zi; }
                    }
                }
            }
        }
        float cum = 0.0f, csel = 0.0f;
        int kc = 1;
#pragma unroll
        for (int r = 1; r <= 16; r++) {
            float v = z[16 - r];
            cum += v;
            if (v * (float)r > cum - 1.0f) { kc = r; csel = cum; }
        }
        float tau = (csel - 1.0f) / (float)kc;
#pragma unroll
        for (int i = 0; i < 16; i++) {
            float p = Ps[lane * PS_STR + i] * inv_alpha() - tau;
            Ps[lane * PS_STR + i] = p > 0.0f ? p : 0.0f;
        }
    }
    __syncwarp();

    // ---- AV via mma: D[16h,64d] = P(16x16,fp16) @ V(16x64,fp16) ----
    {
        const int r4 = lane >> 2;          // 0..7
        const int c2 = (lane & 3) * 2;     // 0,2,4,6
        // build P A-fragment (layout verified against the GEMM ldsm path);
        // PS_STR=18 (even) keeps every float2 8B-aligned.
        uint32_t pf[4];
        {
            float2 v0 = *(float2*)(Ps + r4 * PS_STR + c2);
            float2 v1 = *(float2*)(Ps + (r4 + 8) * PS_STR + c2);
            float2 v2 = *(float2*)(Ps + r4 * PS_STR + c2 + 8);
            float2 v3 = *(float2*)(Ps + (r4 + 8) * PS_STR + c2 + 8);
            __half2 h0 = __floats2half2_rn(v0.x, v0.y);
            __half2 h1 = __floats2half2_rn(v1.x, v1.y);
            __half2 h2 = __floats2half2_rn(v2.x, v2.y);
            __half2 h3 = __floats2half2_rn(v3.x, v3.y);
            pf[0] = *(uint32_t*)&h0; pf[1] = *(uint32_t*)&h1;
            pf[2] = *(uint32_t*)&h2; pf[3] = *(uint32_t*)&h3;
        }
        __syncwarp();   // all lanes done reading Ps before Dst overwrites it

        // V B-fragments via ldsm.trans: V is [k=g][n=d] k-major.
        // lane addr: row = lane&15, ncol = (lane>>4)*8 (+ n16*16 per call)
        const uint32_t sV = smem_u32(Vt);
        const uint32_t vbase = sV + (uint32_t)((lane & 15) * 144)
                                  + (uint32_t)(((lane >> 4) * 8) * 2);
#pragma unroll
        for (int n16 = 0; n16 < 4; n16++) {
            uint32_t vf[4];
            ldsm4t(vf, vbase + (uint32_t)(n16 * 32));
            float D0[4] = {0, 0, 0, 0};
            float D1[4] = {0, 0, 0, 0};
            mma16816(D0, pf, &vf[0]);
            mma16816(D1, pf, &vf[2]);
            const int cb2 = n16 * 16;
            *(float2*)(Dst + r4 * 68 + cb2 + c2)            = make_float2(D0[0], D0[1]);
            *(float2*)(Dst + (r4 + 8) * 68 + cb2 + c2)      = make_float2(D0[2], D0[3]);
            *(float2*)(Dst + r4 * 68 + cb2 + 8 + c2)        = make_float2(D1[0], D1[1]);
            *(float2*)(Dst + (r4 + 8) * 68 + cb2 + 8 + c2)  = make_float2(D1[2], D1[3]);
        }
    }
    __syncwarp();

    // ---- writeout: lane -> (h = lane&15, d-window = (lane>>4)*32) ----
    {
        const int h  = lane & 15;
        const int dw = (lane >> 4) * 32;
        const size_t m2  = ((size_t)(h * 256 + (a >> 4))) * 8 + (size_t)b;
        const int    col = (a & 15) * 64 + dw;
        __half* dst = x2 + m2 * DM + col;
#pragma unroll
        for (int j = 0; j < 8; j++) {
            float4 v = *(const float4*)(Dst + h * 68 + dw + j * 4);
            __half2 p0 = __floats2half2_rn(v.x, v.y);
            __half2 p1 = __floats2half2_rn(v.z, v.w);
            *(uint2*)(dst + j * 4) = make_uint2(*(uint32_t*)&p0, *(uint32_t*)&p1);
        }
    }
}

// ---------------- launcher ----------------
extern "C" void kernel_launch(void* const* d_in, const int* in_sizes, int n_in,
                              void* d_out, int out_size)
{
    (void)in_sizes; (void)n_in; (void)out_size;

    void *pah, *pwh, *pq, *pk, *pv, *px2;
    cudaGetSymbolAddress(&pah, g_ah);
    cudaGetSymbolAddress(&pwh, g_wh);
    cudaGetSymbolAddress(&pq,  g_q);
    cudaGetSymbolAddress(&pk,  g_k);
    cudaGetSymbolAddress(&pv,  g_v);
    cudaGetSymbolAddress(&px2, g_x2);

    __half* ah   = (__half*)pah;
    __half* wh   = (__half*)pwh;
    __half* qbuf = (__half*)pq;
    __half* kbuf = (__half*)pk;
    __half* vbuf = (__half*)pv;
    __half* x2   = (__half*)px2;

    cudaFuncSetAttribute(gemm_qkv, cudaFuncAttributeMaxDynamicSharedMemorySize, GEMM_SMEM);
    cudaFuncSetAttribute(gemm_out, cudaFuncAttributeMaxDynamicSharedMemorySize, GEMM_SMEM);
    cudaFuncSetAttribute(attn_kernel, cudaFuncAttributeMaxDynamicSharedMemorySize, ATT_SMEM);

    // 1) convert activations (query/key/value) to fp16 — one launch
    const int actN8 = (int)(NELEM_ACT / 8);
    conv3_fp16_kernel<<<dim3(actN8 / 512, 3), 256>>>(
        (const float4*)d_in[0], (const float4*)d_in[1], (const float4*)d_in[2],
        (uint4*)ah, actN8);

    // 2) convert weights (Wq,Wk,Wv,Wo) to fp16 — one launch
    const int wN8 = (int)(NELEM_W / 8);
    conv4_fp16_kernel<<<dim3(wN8 / 256, 4), 256>>>(
        (const float4*)d_in[3], (const float4*)d_in[5],
        (const float4*)d_in[7], (const float4*)d_in[9],
        (uint4*)wh, wN8);

    // 3) Q+K+V projections in ONE launch (grid.z = 3); N-fastest for A reuse
    dim3 qkvgrid(DM / BN, MROWS / BM, 3);   // (8, 256, 3)
    gemm_qkv<<<qkvgrid, 128, GEMM_SMEM>>>(
        ah, wh,
        (const float*)d_in[4], (const float*)d_in[6], (const float*)d_in[8],
        qbuf, kbuf, vbuf);

    // 4) sparsemax attention (tensor-core scores + AV) -> permuted X2 (fp16)
    attn_kernel<<<MROWS / 8, 256, ATT_SMEM>>>(qbuf, kbuf, vbuf, x2);

    // 5) output projection straight into d_out (fp32)
    dim3 ggrid(DM / BN, MROWS / BM);        // (8, 256)
    gemm_out<<<ggrid, 128, GEMM_SMEM>>>(
        x2, wh + 3 * NELEM_W, (const float*)d_in[10], (float*)d_out);
}